// round 5
// baseline (speedup 1.0000x reference)
#include <cuda_runtime.h>
#include <cuda_fp16.h>
#include <math.h>
#include <cstdint>

#define HW      96
#define NPIX    9216
#define NCH     21
#define RAD     35
#define KW      71
#define KSPLIT  2
#define KHALF   4608
#define CHUNK   128           // k per pipeline chunk (2 panels of 64)
#define NCHUNK  36            // KHALF / CHUNK
#define NSTAGE  5
#define PANEL_A 16384         // 128 rows * 128B
#define PANEL_B 4096          // 32 rows * 128B
#define STAGE_BYTES 40960     // 2*PANEL_A + 2*PANEL_B
#define MTILES  72
#define GEMM_SMEM (NSTAGE * STAGE_BYTES + 1024)

// ---------------- device scratch ----------------
__device__ __half g_Kh[(size_t)NPIX * NPIX];
__device__ float  g_feat[5][NPIX];
__device__ float  g_rowpart[NPIX * MTILES];
__device__ float  g_rowinv[NPIX];
__device__ float  g_U[NCH * NPIX];
__device__ float  g_q[NCH * NPIX];
__device__ __half g_qh[32 * NPIX];
__device__ float  g_part[KSPLIT * NCH * NPIX];
__device__ float  g_qsf[NCH * NPIX];
__device__ float  g_g1d[KW];

// ---------------- PTX helpers ----------------
__device__ __forceinline__ uint32_t s2u(const void* p) {
    uint32_t a;
    asm("{ .reg .u64 t; cvta.to.shared.u64 t, %1; cvt.u32.u64 %0, t; }" : "=r"(a) : "l"(p));
    return a;
}
#define SWZ(b) ((b) ^ (((b) >> 3) & 0x70))
#define CP16(dst, src) \
    asm volatile("cp.async.cg.shared.global [%0], [%1], 16;" :: "r"(dst), "l"(src) : "memory")
#define CP_COMMIT() asm volatile("cp.async.commit_group;" ::: "memory")
#define CP_WAIT(n)  asm volatile("cp.async.wait_group %0;" :: "n"(n) : "memory")
#define LDSM4(r0, r1, r2, r3, addr) \
    asm volatile("ldmatrix.sync.aligned.m8n8.x4.shared.b16 {%0,%1,%2,%3}, [%4];" \
                 : "=r"(r0), "=r"(r1), "=r"(r2), "=r"(r3) : "r"(addr))
#define LDSM2(r0, r1, addr) \
    asm volatile("ldmatrix.sync.aligned.m8n8.x2.shared.b16 {%0,%1}, [%2];" \
                 : "=r"(r0), "=r"(r1) : "r"(addr))
#define MMA16816(d, a0, a1, a2, a3, b0, b1) \
    asm volatile("mma.sync.aligned.m16n8k16.row.col.f32.f16.f16.f32 " \
                 "{%0,%1,%2,%3}, {%4,%5,%6,%7}, {%8,%9}, {%0,%1,%2,%3};" \
                 : "+f"((d)[0]), "+f"((d)[1]), "+f"((d)[2]), "+f"((d)[3]) \
                 : "r"(a0), "r"(a1), "r"(a2), "r"(a3), "r"(b0), "r"(b1))

// ---------------- setup ----------------
__global__ void k_feat(const float* __restrict__ ref, const float* __restrict__ kstd) {
    if (blockIdx.x == 0 && threadIdx.x == 0) {
        float w[KW]; float s = 0.f;
        for (int t = 0; t < KW; ++t) {
            float d = (float)t - (float)RAD;
            w[t] = expf(-(d * d) / 72.0f); s += w[t];
        }
        float inv = 1.0f / s;
        for (int t = 0; t < KW; ++t) g_g1d[t] = w[t] * inv;
    }
    int i = blockIdx.x * blockDim.x + threadIdx.x;
    if (i >= NPIX) return;
    int y = i / HW, x = i % HW;
    g_feat[0][i] = (float)y / kstd[0];
    g_feat[1][i] = (float)x / kstd[1];
    g_feat[2][i] = ref[0 * NPIX + i] / kstd[2];
    g_feat[3][i] = ref[1 * NPIX + i] / kstd[3];
    g_feat[4][i] = ref[2 * NPIX + i] / kstd[4];
}

__global__ void __launch_bounds__(256) k_K() {
    __shared__ float s_fr[5][32];
    __shared__ float s_fc[5][128];
    const int rowBase = blockIdx.y * 32;
    const int colBase = blockIdx.x * 128;
    const int tid = threadIdx.x;

    if (tid < 5 * 32) { int d = tid / 32, rr = tid % 32; s_fr[d][rr] = g_feat[d][rowBase + rr]; }
    for (int idx = tid; idx < 5 * 128; idx += 256) {
        int d = idx / 128, cc = idx % 128;
        s_fc[d][cc] = g_feat[d][colBase + cc];
    }
    __syncthreads();

    const int r = tid >> 5;
    const int cl = tid & 31;

    float fr[4][5], fc[4][5];
#pragma unroll
    for (int a = 0; a < 4; ++a)
#pragma unroll
        for (int d = 0; d < 5; ++d) fr[a][d] = s_fr[d][r * 4 + a];
#pragma unroll
    for (int b = 0; b < 4; ++b)
#pragma unroll
        for (int d = 0; d < 5; ++d) fc[b][d] = s_fc[d][cl + 32 * b];

#pragma unroll
    for (int a = 0; a < 4; ++a) {
        const int row = rowBase + r * 4 + a;
        const size_t rowOff = (size_t)row * NPIX;
        float rs = 0.f;
#pragma unroll
        for (int b = 0; b < 4; ++b) {
            float d2 = 0.f;
#pragma unroll
            for (int d = 0; d < 5; ++d) {
                float df = fr[a][d] - fc[b][d];
                d2 = fmaf(df, df, d2);
            }
            float v = __expf(-0.5f * d2);
            rs += v;
            g_Kh[rowOff + colBase + cl + 32 * b] = __float2half_rn(v);
        }
#pragma unroll
        for (int o = 16; o; o >>= 1) rs += __shfl_xor_sync(0xffffffffu, rs, o);
        if (cl == 0) g_rowpart[row * MTILES + blockIdx.x] = rs;
    }
}

__global__ void k_init(const float* __restrict__ unary) {
    int i = blockIdx.x * blockDim.x + threadIdx.x;
    if (i >= NPIX) return;
    float s = 0.f;
    const float* p = g_rowpart + i * MTILES;
#pragma unroll
    for (int b = 0; b < MTILES; ++b) s += p[b];
    float ri = 1.0f / (sqrtf(s) + 1e-8f);
    g_rowinv[i] = ri;

    float L[NCH];
    float m = -1e30f;
#pragma unroll
    for (int c = 0; c < NCH; ++c) {
        float u = unary[c * NPIX + i];
        u = fminf(fmaxf(u, 1e-5f), 1.0f);
        float lu = logf(u);
        g_U[c * NPIX + i] = lu;
        L[c] = lu;
        m = fmaxf(m, lu);
    }
    float se = 0.f;
#pragma unroll
    for (int c = 0; c < NCH; ++c) { L[c] = __expf(L[c] - m); se += L[c]; }
    float inv = 1.0f / se;
#pragma unroll
    for (int c = 0; c < NCH; ++c) {
        float q = L[c] * inv;
        g_q[c * NPIX + i] = q;
        g_qh[c * NPIX + i] = __float2half_rn(q * ri);
    }
#pragma unroll
    for (int c = NCH; c < 32; ++c) g_qh[c * NPIX + i] = __float2half_rn(0.f);
}

// ---------------- fused separable spatial conv: 1 block per channel ----------------
__global__ void __launch_bounds__(256) k_conv() {
    extern __shared__ float sm[];
    float* sImg = sm;            // 9216 floats
    float* sTmp = sm + NPIX;     // 9216 floats
    __shared__ float sW[KW];
    const int c = blockIdx.x;
    const int tid = threadIdx.x;

    if (tid < KW) sW[tid] = g_g1d[tid];
    for (int p = tid; p < NPIX; p += 256) sImg[p] = g_q[c * NPIX + p];
    __syncthreads();

    // Y pass
    for (int p = tid; p < NPIX; p += 256) {
        int y = p / HW, x = p % HW;
        int t0 = max(-RAD, -y), t1 = min(RAD, HW - 1 - y);
        float s = 0.f;
        for (int t = t0; t <= t1; ++t)
            s = fmaf(sW[t + RAD], sImg[(y + t) * HW + x], s);
        sTmp[p] = s;
    }
    __syncthreads();

    // X pass
    for (int p = tid; p < NPIX; p += 256) {
        int y = p / HW, x = p % HW;
        int t0 = max(-RAD, -x), t1 = min(RAD, HW - 1 - x);
        float s = 0.f;
        for (int t = t0; t <= t1; ++t)
            s = fmaf(sW[t + RAD], sTmp[y * HW + x + t], s);
        g_qsf[c * NPIX + p] = s;
    }
}

// ---------------- HMMA split-K GEMM, single-barrier pipeline ----------------
__global__ void __launch_bounds__(256, 1) k_gemm_mma() {
    extern __shared__ char dynRaw[];
    const uint32_t dynb = (s2u(dynRaw) + 1023u) & ~1023u;
    const int tid = threadIdx.x, w = tid >> 5, lid = tid & 31;
    const int m0 = blockIdx.x * 128;
    const int zbase = blockIdx.y * KHALF;

    const __half* Abase = g_Kh + (size_t)m0 * NPIX + zbase;
    const __half* Bbase = g_qh + zbase;

    auto load_chunk = [&](int ci) {
        const uint32_t stage = dynb + (uint32_t)(ci % NSTAGE) * STAGE_BYTES;
        const int koff = ci * CHUNK;
#pragma unroll
        for (int pl = 0; pl < 2; ++pl) {
            const uint32_t bufA = stage + (uint32_t)pl * PANEL_A;
            const uint32_t bufB = stage + 2 * PANEL_A + (uint32_t)pl * PANEL_B;
            const int kof = koff + pl * 64;
#pragma unroll
            for (int u = tid; u < 1280; u += 256) {
                uint32_t dst; const void* src;
                if (u < 1024) {
                    int r = u >> 3, t = u & 7;
                    src = Abase + (size_t)r * NPIX + kof + t * 8;
                    dst = bufA + SWZ((uint32_t)(r * 128 + t * 16));
                } else {
                    int v = u - 1024;
                    int cc = v >> 3, t = v & 7;
                    src = Bbase + (size_t)cc * NPIX + kof + t * 8;
                    dst = bufB + SWZ((uint32_t)(cc * 128 + t * 16));
                }
                CP16(dst, src);
            }
        }
        CP_COMMIT();
    };

    float acc[3][4];
#pragma unroll
    for (int g = 0; g < 3; ++g)
#pragma unroll
        for (int k = 0; k < 4; ++k) acc[g][k] = 0.f;

    for (int i = 0; i < NSTAGE - 1; ++i) load_chunk(i);

    const uint32_t aRowOff = (uint32_t)((w * 16 + (lid & 15)) * 128) + ((lid >> 4) << 4);
    const uint32_t bRowOff01 = (uint32_t)(((lid & 7) + ((lid >> 4) << 3)) * 128) + (((lid >> 3) & 1) << 4);
    const uint32_t bRowOff2 = (uint32_t)((16 + (lid & 7)) * 128) + (((lid >> 3) & 1) << 4);

    for (int i = 0; i < NCHUNK; ++i) {
        if (i + NSTAGE - 1 < NCHUNK) CP_WAIT(NSTAGE - 2); else CP_WAIT(0);
        __syncthreads();
        if (i + NSTAGE - 1 < NCHUNK) load_chunk(i + NSTAGE - 1);

        const uint32_t stage = dynb + (uint32_t)(i % NSTAGE) * STAGE_BYTES;
#pragma unroll
        for (int pl = 0; pl < 2; ++pl) {
            const uint32_t bufA = stage + (uint32_t)pl * PANEL_A;
            const uint32_t bufB = stage + 2 * PANEL_A + (uint32_t)pl * PANEL_B;
#pragma unroll
            for (int ks = 0; ks < 4; ++ks) {
                const uint32_t kb = (uint32_t)ks * 32;
                uint32_t a0, a1, a2, a3;
                LDSM4(a0, a1, a2, a3, bufA + SWZ(aRowOff + kb));
                uint32_t b00, b01, b10, b11, b20, b21;
                LDSM4(b00, b01, b10, b11, bufB + SWZ(bRowOff01 + kb));
                LDSM2(b20, b21, bufB + SWZ(bRowOff2 + kb));
                MMA16816(acc[0], a0, a1, a2, a3, b00, b01);
                MMA16816(acc[1], a0, a1, a2, a3, b10, b11);
                MMA16816(acc[2], a0, a1, a2, a3, b20, b21);
            }
        }
    }

    const int row0 = m0 + w * 16 + (lid >> 2);
    const int c0 = (lid & 3) * 2;
    float* pp = g_part + (size_t)blockIdx.y * (NCH * NPIX);
#pragma unroll
    for (int g = 0; g < 3; ++g) {
#pragma unroll
        for (int k = 0; k < 4; ++k) {
            int c = g * 8 + c0 + (k & 1);
            int row = row0 + ((k >> 1) << 3);
            if (c < NCH) pp[c * NPIX + row] = acc[g][k];
        }
    }
}

// ---------------- softmax update ----------------
__global__ void k_update(float* __restrict__ out, int final_it) {
    int i = blockIdx.x * blockDim.x + threadIdx.x;
    if (i >= NPIX) return;
    float ri = g_rowinv[i];
    float* dst = final_it ? out : g_q;

    float L[NCH];
    float m = -1e30f;
#pragma unroll
    for (int c = 0; c < NCH; ++c) {
        float s = g_part[c * NPIX + i] + g_part[(NCH + c) * NPIX + i];
        float l = g_U[c * NPIX + i] + 4.0f * (s * ri) + 2.0f * g_qsf[c * NPIX + i];
        L[c] = l;
        m = fmaxf(m, l);
    }
    float se = 0.f;
#pragma unroll
    for (int c = 0; c < NCH; ++c) { L[c] = __expf(L[c] - m); se += L[c]; }
    float inv = 1.0f / se;
#pragma unroll
    for (int c = 0; c < NCH; ++c) {
        float q = L[c] * inv;
        dst[c * NPIX + i] = q;
        g_qh[c * NPIX + i] = __float2half_rn(q * ri);
    }
}

// ---------------- launch ----------------
extern "C" void kernel_launch(void* const* d_in, const int* in_sizes, int n_in,
                              void* d_out, int out_size) {
    const float* unary = nullptr;
    const float* ref = nullptr;
    const float* kstd = nullptr;
    for (int i = 0; i < n_in; ++i) {
        if (in_sizes[i] == NCH * NPIX) unary = (const float*)d_in[i];
        else if (in_sizes[i] == 3 * NPIX) ref = (const float*)d_in[i];
        else if (in_sizes[i] == 5) kstd = (const float*)d_in[i];
    }

    cudaFuncSetAttribute(k_gemm_mma, cudaFuncAttributeMaxDynamicSharedMemorySize, GEMM_SMEM);
    cudaFuncSetAttribute(k_conv, cudaFuncAttributeMaxDynamicSharedMemorySize,
                         2 * NPIX * (int)sizeof(float));

    k_feat<<<(NPIX + 255) / 256, 256>>>(ref, kstd);
    k_K<<<dim3(NPIX / 128, NPIX / 32), 256>>>();
    k_init<<<(NPIX + 255) / 256, 256>>>(unary);

    for (int it = 0; it < 5; ++it) {
        k_conv<<<NCH, 256, 2 * NPIX * sizeof(float)>>>();
        k_gemm_mma<<<dim3(MTILES, KSPLIT), 256, GEMM_SMEM>>>();
        k_update<<<(NPIX + 255) / 256, 256>>>((float*)d_out, it == 4 ? 1 : 0);
    }
}

// round 6
// speedup vs baseline: 1.5637x; 1.5637x over previous
#include <cuda_runtime.h>
#include <cuda_fp16.h>
#include <math.h>
#include <cstdint>

#define HW      96
#define NPIX    9216
#define NCH     21
#define RAD     35
#define KW      71
#define KSPLIT  2
#define KHALF   4608
#define CHUNK   128           // k per pipeline chunk (2 panels of 64)
#define NCHUNK  36            // KHALF / CHUNK
#define NSTAGE  5
#define PANEL_A 16384         // 128 rows * 128B
#define PANEL_B 4096          // 32 rows * 128B
#define STAGE_BYTES 40960     // 2*PANEL_A + 2*PANEL_B
#define MTILES  72
#define GEMM_SMEM (NSTAGE * STAGE_BYTES + 1024)
#define STRIPS  6
#define SROWS   16            // output rows per strip
#define HALO    86            // max input rows per strip (16 + 2*35)

// ---------------- device scratch ----------------
__device__ __half g_Kh[(size_t)NPIX * NPIX];
__device__ float  g_feat[5][NPIX];
__device__ float  g_rowpart[NPIX * MTILES];
__device__ float  g_rowinv[NPIX];
__device__ float  g_U[NCH * NPIX];
__device__ float  g_q[NCH * NPIX];
__device__ __half g_qh[32 * NPIX];
__device__ float  g_part[KSPLIT * NCH * NPIX];
__device__ float  g_qsf[NCH * NPIX];
__device__ float  g_g1d[KW];

// ---------------- PTX helpers ----------------
__device__ __forceinline__ uint32_t s2u(const void* p) {
    uint32_t a;
    asm("{ .reg .u64 t; cvta.to.shared.u64 t, %1; cvt.u32.u64 %0, t; }" : "=r"(a) : "l"(p));
    return a;
}
#define SWZ(b) ((b) ^ (((b) >> 3) & 0x70))
#define CP16(dst, src) \
    asm volatile("cp.async.cg.shared.global [%0], [%1], 16;" :: "r"(dst), "l"(src) : "memory")
#define CP_COMMIT() asm volatile("cp.async.commit_group;" ::: "memory")
#define CP_WAIT(n)  asm volatile("cp.async.wait_group %0;" :: "n"(n) : "memory")
#define LDSM4(r0, r1, r2, r3, addr) \
    asm volatile("ldmatrix.sync.aligned.m8n8.x4.shared.b16 {%0,%1,%2,%3}, [%4];" \
                 : "=r"(r0), "=r"(r1), "=r"(r2), "=r"(r3) : "r"(addr))
#define LDSM2(r0, r1, addr) \
    asm volatile("ldmatrix.sync.aligned.m8n8.x2.shared.b16 {%0,%1}, [%2];" \
                 : "=r"(r0), "=r"(r1) : "r"(addr))
#define MMA16816(d, a0, a1, a2, a3, b0, b1) \
    asm volatile("mma.sync.aligned.m16n8k16.row.col.f32.f16.f16.f32 " \
                 "{%0,%1,%2,%3}, {%4,%5,%6,%7}, {%8,%9}, {%0,%1,%2,%3};" \
                 : "+f"((d)[0]), "+f"((d)[1]), "+f"((d)[2]), "+f"((d)[3]) \
                 : "r"(a0), "r"(a1), "r"(a2), "r"(a3), "r"(b0), "r"(b1))

// ---------------- setup ----------------
__global__ void k_feat(const float* __restrict__ ref, const float* __restrict__ kstd) {
    if (blockIdx.x == 0 && threadIdx.x == 0) {
        float w[KW]; float s = 0.f;
        for (int t = 0; t < KW; ++t) {
            float d = (float)t - (float)RAD;
            w[t] = expf(-(d * d) / 72.0f); s += w[t];
        }
        float inv = 1.0f / s;
        for (int t = 0; t < KW; ++t) g_g1d[t] = w[t] * inv;
    }
    int i = blockIdx.x * blockDim.x + threadIdx.x;
    if (i >= NPIX) return;
    int y = i / HW, x = i % HW;
    g_feat[0][i] = (float)y / kstd[0];
    g_feat[1][i] = (float)x / kstd[1];
    g_feat[2][i] = ref[0 * NPIX + i] / kstd[2];
    g_feat[3][i] = ref[1 * NPIX + i] / kstd[3];
    g_feat[4][i] = ref[2 * NPIX + i] / kstd[4];
}

__global__ void __launch_bounds__(256) k_K() {
    __shared__ float s_fr[5][32];
    __shared__ float s_fc[5][128];
    const int rowBase = blockIdx.y * 32;
    const int colBase = blockIdx.x * 128;
    const int tid = threadIdx.x;

    if (tid < 5 * 32) { int d = tid / 32, rr = tid % 32; s_fr[d][rr] = g_feat[d][rowBase + rr]; }
    for (int idx = tid; idx < 5 * 128; idx += 256) {
        int d = idx / 128, cc = idx % 128;
        s_fc[d][cc] = g_feat[d][colBase + cc];
    }
    __syncthreads();

    const int r = tid >> 5;
    const int cl = tid & 31;

    float fr[4][5], fc[4][5];
#pragma unroll
    for (int a = 0; a < 4; ++a)
#pragma unroll
        for (int d = 0; d < 5; ++d) fr[a][d] = s_fr[d][r * 4 + a];
#pragma unroll
    for (int b = 0; b < 4; ++b)
#pragma unroll
        for (int d = 0; d < 5; ++d) fc[b][d] = s_fc[d][cl + 32 * b];

#pragma unroll
    for (int a = 0; a < 4; ++a) {
        const int row = rowBase + r * 4 + a;
        const size_t rowOff = (size_t)row * NPIX;
        float rs = 0.f;
#pragma unroll
        for (int b = 0; b < 4; ++b) {
            float d2 = 0.f;
#pragma unroll
            for (int d = 0; d < 5; ++d) {
                float df = fr[a][d] - fc[b][d];
                d2 = fmaf(df, df, d2);
            }
            float v = __expf(-0.5f * d2);
            rs += v;
            g_Kh[rowOff + colBase + cl + 32 * b] = __float2half_rn(v);
        }
#pragma unroll
        for (int o = 16; o; o >>= 1) rs += __shfl_xor_sync(0xffffffffu, rs, o);
        if (cl == 0) g_rowpart[row * MTILES + blockIdx.x] = rs;
    }
}

__global__ void k_init(const float* __restrict__ unary) {
    int i = blockIdx.x * blockDim.x + threadIdx.x;
    if (i >= NPIX) return;
    float s = 0.f;
    const float* p = g_rowpart + i * MTILES;
#pragma unroll
    for (int b = 0; b < MTILES; ++b) s += p[b];
    float ri = 1.0f / (sqrtf(s) + 1e-8f);
    g_rowinv[i] = ri;

    float L[NCH];
    float m = -1e30f;
#pragma unroll
    for (int c = 0; c < NCH; ++c) {
        float u = unary[c * NPIX + i];
        u = fminf(fmaxf(u, 1e-5f), 1.0f);
        float lu = logf(u);
        g_U[c * NPIX + i] = lu;
        L[c] = lu;
        m = fmaxf(m, lu);
    }
    float se = 0.f;
#pragma unroll
    for (int c = 0; c < NCH; ++c) { L[c] = __expf(L[c] - m); se += L[c]; }
    float inv = 1.0f / se;
#pragma unroll
    for (int c = 0; c < NCH; ++c) {
        float q = L[c] * inv;
        g_q[c * NPIX + i] = q;
        g_qh[c * NPIX + i] = __float2half_rn(q * ri);
    }
#pragma unroll
    for (int c = NCH; c < 32; ++c) g_qh[c * NPIX + i] = __float2half_rn(0.f);
}

// ---------------- strip-parallel separable spatial conv ----------------
// grid = NCH * STRIPS (126 CTAs); each CTA: 16 output rows of one channel.
__global__ void __launch_bounds__(256) k_conv() {
    __shared__ float sImg[HALO * HW];   // input rows incl. halo
    __shared__ float sTmp[SROWS * HW];  // Y-pass result
    __shared__ float sW[KW];
    const int c = blockIdx.x / STRIPS;
    const int strip = blockIdx.x % STRIPS;
    const int y0 = strip * SROWS;
    const int rowLo = max(0, y0 - RAD);
    const int rowHi = min(HW - 1, y0 + SROWS - 1 + RAD);
    const int nrows = rowHi - rowLo + 1;
    const int tid = threadIdx.x;

    if (tid < KW) sW[tid] = g_g1d[tid];
    const float* src = g_q + c * NPIX + rowLo * HW;
    for (int p = tid; p < nrows * HW; p += 256) sImg[p] = src[p];
    __syncthreads();

    // Y pass: outputs rows y0..y0+15
    for (int p = tid; p < SROWS * HW; p += 256) {
        int yy = p / HW, x = p % HW;
        int y = y0 + yy;
        int t0 = max(-RAD, -y), t1 = min(RAD, HW - 1 - y);
        float s = 0.f;
        const float* col = sImg + (y - rowLo) * HW + x;
        for (int t = t0; t <= t1; ++t)
            s = fmaf(sW[t + RAD], col[t * HW], s);
        sTmp[p] = s;
    }
    __syncthreads();

    // X pass
    float* dst = g_qsf + c * NPIX + y0 * HW;
    for (int p = tid; p < SROWS * HW; p += 256) {
        int yy = p / HW, x = p % HW;
        int t0 = max(-RAD, -x), t1 = min(RAD, HW - 1 - x);
        float s = 0.f;
        const float* row = sTmp + yy * HW + x;
        for (int t = t0; t <= t1; ++t)
            s = fmaf(sW[t + RAD], row[t], s);
        dst[p] = s;
    }
}

// ---------------- HMMA split-K GEMM, single-barrier pipeline ----------------
__global__ void __launch_bounds__(256, 1) k_gemm_mma() {
    extern __shared__ char dynRaw[];
    const uint32_t dynb = (s2u(dynRaw) + 1023u) & ~1023u;
    const int tid = threadIdx.x, w = tid >> 5, lid = tid & 31;
    const int m0 = blockIdx.x * 128;
    const int zbase = blockIdx.y * KHALF;

    const __half* Abase = g_Kh + (size_t)m0 * NPIX + zbase;
    const __half* Bbase = g_qh + zbase;

    auto load_chunk = [&](int ci) {
        const uint32_t stage = dynb + (uint32_t)(ci % NSTAGE) * STAGE_BYTES;
        const int koff = ci * CHUNK;
#pragma unroll
        for (int pl = 0; pl < 2; ++pl) {
            const uint32_t bufA = stage + (uint32_t)pl * PANEL_A;
            const uint32_t bufB = stage + 2 * PANEL_A + (uint32_t)pl * PANEL_B;
            const int kof = koff + pl * 64;
#pragma unroll
            for (int u = tid; u < 1280; u += 256) {
                uint32_t dst; const void* src;
                if (u < 1024) {
                    int r = u >> 3, t = u & 7;
                    src = Abase + (size_t)r * NPIX + kof + t * 8;
                    dst = bufA + SWZ((uint32_t)(r * 128 + t * 16));
                } else {
                    int v = u - 1024;
                    int cc = v >> 3, t = v & 7;
                    src = Bbase + (size_t)cc * NPIX + kof + t * 8;
                    dst = bufB + SWZ((uint32_t)(cc * 128 + t * 16));
                }
                CP16(dst, src);
            }
        }
        CP_COMMIT();
    };

    float acc[3][4];
#pragma unroll
    for (int g = 0; g < 3; ++g)
#pragma unroll
        for (int k = 0; k < 4; ++k) acc[g][k] = 0.f;

    for (int i = 0; i < NSTAGE - 1; ++i) load_chunk(i);

    const uint32_t aRowOff = (uint32_t)((w * 16 + (lid & 15)) * 128) + ((lid >> 4) << 4);
    const uint32_t bRowOff01 = (uint32_t)(((lid & 7) + ((lid >> 4) << 3)) * 128) + (((lid >> 3) & 1) << 4);
    const uint32_t bRowOff2 = (uint32_t)((16 + (lid & 7)) * 128) + (((lid >> 3) & 1) << 4);

    for (int i = 0; i < NCHUNK; ++i) {
        if (i + NSTAGE - 1 < NCHUNK) CP_WAIT(NSTAGE - 2); else CP_WAIT(0);
        __syncthreads();
        if (i + NSTAGE - 1 < NCHUNK) load_chunk(i + NSTAGE - 1);

        const uint32_t stage = dynb + (uint32_t)(i % NSTAGE) * STAGE_BYTES;
#pragma unroll
        for (int pl = 0; pl < 2; ++pl) {
            const uint32_t bufA = stage + (uint32_t)pl * PANEL_A;
            const uint32_t bufB = stage + 2 * PANEL_A + (uint32_t)pl * PANEL_B;
#pragma unroll
            for (int ks = 0; ks < 4; ++ks) {
                const uint32_t kb = (uint32_t)ks * 32;
                uint32_t a0, a1, a2, a3;
                LDSM4(a0, a1, a2, a3, bufA + SWZ(aRowOff + kb));
                uint32_t b00, b01, b10, b11, b20, b21;
                LDSM4(b00, b01, b10, b11, bufB + SWZ(bRowOff01 + kb));
                LDSM2(b20, b21, bufB + SWZ(bRowOff2 + kb));
                MMA16816(acc[0], a0, a1, a2, a3, b00, b01);
                MMA16816(acc[1], a0, a1, a2, a3, b10, b11);
                MMA16816(acc[2], a0, a1, a2, a3, b20, b21);
            }
        }
    }

    const int row0 = m0 + w * 16 + (lid >> 2);
    const int c0 = (lid & 3) * 2;
    float* pp = g_part + (size_t)blockIdx.y * (NCH * NPIX);
#pragma unroll
    for (int g = 0; g < 3; ++g) {
#pragma unroll
        for (int k = 0; k < 4; ++k) {
            int c = g * 8 + c0 + (k & 1);
            int row = row0 + ((k >> 1) << 3);
            if (c < NCH) pp[c * NPIX + row] = acc[g][k];
        }
    }
}

// ---------------- softmax update ----------------
__global__ void k_update(float* __restrict__ out, int final_it) {
    int i = blockIdx.x * blockDim.x + threadIdx.x;
    if (i >= NPIX) return;
    float ri = g_rowinv[i];
    float* dst = final_it ? out : g_q;

    float L[NCH];
    float m = -1e30f;
#pragma unroll
    for (int c = 0; c < NCH; ++c) {
        float s = g_part[c * NPIX + i] + g_part[(NCH + c) * NPIX + i];
        float l = g_U[c * NPIX + i] + 4.0f * (s * ri) + 2.0f * g_qsf[c * NPIX + i];
        L[c] = l;
        m = fmaxf(m, l);
    }
    float se = 0.f;
#pragma unroll
    for (int c = 0; c < NCH; ++c) { L[c] = __expf(L[c] - m); se += L[c]; }
    float inv = 1.0f / se;
#pragma unroll
    for (int c = 0; c < NCH; ++c) {
        float q = L[c] * inv;
        dst[c * NPIX + i] = q;
        g_qh[c * NPIX + i] = __float2half_rn(q * ri);
    }
}

// ---------------- launch ----------------
extern "C" void kernel_launch(void* const* d_in, const int* in_sizes, int n_in,
                              void* d_out, int out_size) {
    const float* unary = nullptr;
    const float* ref = nullptr;
    const float* kstd = nullptr;
    for (int i = 0; i < n_in; ++i) {
        if (in_sizes[i] == NCH * NPIX) unary = (const float*)d_in[i];
        else if (in_sizes[i] == 3 * NPIX) ref = (const float*)d_in[i];
        else if (in_sizes[i] == 5) kstd = (const float*)d_in[i];
    }

    cudaFuncSetAttribute(k_gemm_mma, cudaFuncAttributeMaxDynamicSharedMemorySize, GEMM_SMEM);

    k_feat<<<(NPIX + 255) / 256, 256>>>(ref, kstd);
    k_K<<<dim3(NPIX / 128, NPIX / 32), 256>>>();
    k_init<<<(NPIX + 255) / 256, 256>>>(unary);

    for (int it = 0; it < 5; ++it) {
        k_conv<<<NCH * STRIPS, 256>>>();
        k_gemm_mma<<<dim3(MTILES, KSPLIT), 256, GEMM_SMEM>>>();
        k_update<<<(NPIX + 255) / 256, 256>>>((float*)d_out, it == 4 ? 1 : 0);
    }
}

// round 7
// speedup vs baseline: 1.6865x; 1.0786x over previous
#include <cuda_runtime.h>
#include <cuda_fp16.h>
#include <math.h>
#include <cstdint>

#define HW      96
#define NPIX    9216
#define NCH     21
#define RAD     35
#define KW      71
#define KSPLIT  2
#define KHALF   4608
#define CHUNK   128           // k per pipeline chunk (2 panels of 64)
#define NCHUNK  36            // KHALF / CHUNK
#define NSTAGE  5
#define PANEL_A 16384         // 128 rows * 128B
#define PANEL_B 4096          // 32 rows * 128B
#define STAGE_BYTES 40960     // 2*PANEL_A + 2*PANEL_B
#define MTILES  72
#define GEMM_SMEM (NSTAGE * STAGE_BYTES + 1024)
#define STRIPS  6
#define SROWS   16            // output rows per strip
#define HALO    86            // 16 + 2*35 input rows (fixed window, zero-padded)
#define TROW    (HW + 2 * RAD) // 166: padded tmp row

// ---------------- device scratch ----------------
__device__ __half g_Kh[(size_t)NPIX * NPIX];
__device__ float  g_feat[5][NPIX];
__device__ float  g_rowpart[NPIX * MTILES];
__device__ float  g_rowinv[NPIX];
__device__ float  g_U[NCH * NPIX];
__device__ float  g_q[NCH * NPIX];
__device__ __half g_qh[32 * NPIX];
__device__ float  g_part[KSPLIT * NCH * NPIX];
__device__ float  g_qsf[NCH * NPIX];
__device__ float  g_g1d[KW];

// ---------------- PTX helpers ----------------
__device__ __forceinline__ uint32_t s2u(const void* p) {
    uint32_t a;
    asm("{ .reg .u64 t; cvta.to.shared.u64 t, %1; cvt.u32.u64 %0, t; }" : "=r"(a) : "l"(p));
    return a;
}
#define SWZ(b) ((b) ^ (((b) >> 3) & 0x70))
#define CP16(dst, src) \
    asm volatile("cp.async.cg.shared.global [%0], [%1], 16;" :: "r"(dst), "l"(src) : "memory")
#define CP_COMMIT() asm volatile("cp.async.commit_group;" ::: "memory")
#define CP_WAIT(n)  asm volatile("cp.async.wait_group %0;" :: "n"(n) : "memory")
#define LDSM4(r0, r1, r2, r3, addr) \
    asm volatile("ldmatrix.sync.aligned.m8n8.x4.shared.b16 {%0,%1,%2,%3}, [%4];" \
                 : "=r"(r0), "=r"(r1), "=r"(r2), "=r"(r3) : "r"(addr))
#define LDSM2(r0, r1, addr) \
    asm volatile("ldmatrix.sync.aligned.m8n8.x2.shared.b16 {%0,%1}, [%2];" \
                 : "=r"(r0), "=r"(r1) : "r"(addr))
#define MMA16816(d, a0, a1, a2, a3, b0, b1) \
    asm volatile("mma.sync.aligned.m16n8k16.row.col.f32.f16.f16.f32 " \
                 "{%0,%1,%2,%3}, {%4,%5,%6,%7}, {%8,%9}, {%0,%1,%2,%3};" \
                 : "+f"((d)[0]), "+f"((d)[1]), "+f"((d)[2]), "+f"((d)[3]) \
                 : "r"(a0), "r"(a1), "r"(a2), "r"(a3), "r"(b0), "r"(b1))

// ---------------- setup ----------------
__global__ void k_feat(const float* __restrict__ ref, const float* __restrict__ kstd) {
    if (blockIdx.x == 0 && threadIdx.x == 0) {
        float w[KW]; float s = 0.f;
        for (int t = 0; t < KW; ++t) {
            float d = (float)t - (float)RAD;
            w[t] = expf(-(d * d) / 72.0f); s += w[t];
        }
        float inv = 1.0f / s;
        for (int t = 0; t < KW; ++t) g_g1d[t] = w[t] * inv;
    }
    int i = blockIdx.x * blockDim.x + threadIdx.x;
    if (i >= NPIX) return;
    int y = i / HW, x = i % HW;
    g_feat[0][i] = (float)y / kstd[0];
    g_feat[1][i] = (float)x / kstd[1];
    g_feat[2][i] = ref[0 * NPIX + i] / kstd[2];
    g_feat[3][i] = ref[1 * NPIX + i] / kstd[3];
    g_feat[4][i] = ref[2 * NPIX + i] / kstd[4];
}

__global__ void __launch_bounds__(256) k_K() {
    __shared__ float s_fr[5][32];
    __shared__ float s_fc[5][128];
    const int rowBase = blockIdx.y * 32;
    const int colBase = blockIdx.x * 128;
    const int tid = threadIdx.x;

    if (tid < 5 * 32) { int d = tid / 32, rr = tid % 32; s_fr[d][rr] = g_feat[d][rowBase + rr]; }
    for (int idx = tid; idx < 5 * 128; idx += 256) {
        int d = idx / 128, cc = idx % 128;
        s_fc[d][cc] = g_feat[d][colBase + cc];
    }
    __syncthreads();

    const int r = tid >> 5;
    const int cl = tid & 31;

    float fr[4][5], fc[4][5];
#pragma unroll
    for (int a = 0; a < 4; ++a)
#pragma unroll
        for (int d = 0; d < 5; ++d) fr[a][d] = s_fr[d][r * 4 + a];
#pragma unroll
    for (int b = 0; b < 4; ++b)
#pragma unroll
        for (int d = 0; d < 5; ++d) fc[b][d] = s_fc[d][cl + 32 * b];

#pragma unroll
    for (int a = 0; a < 4; ++a) {
        const int row = rowBase + r * 4 + a;
        const size_t rowOff = (size_t)row * NPIX;
        float rs = 0.f;
#pragma unroll
        for (int b = 0; b < 4; ++b) {
            float d2 = 0.f;
#pragma unroll
            for (int d = 0; d < 5; ++d) {
                float df = fr[a][d] - fc[b][d];
                d2 = fmaf(df, df, d2);
            }
            float v = __expf(-0.5f * d2);
            rs += v;
            g_Kh[rowOff + colBase + cl + 32 * b] = __float2half_rn(v);
        }
#pragma unroll
        for (int o = 16; o; o >>= 1) rs += __shfl_xor_sync(0xffffffffu, rs, o);
        if (cl == 0) g_rowpart[row * MTILES + blockIdx.x] = rs;
    }
}

__global__ void k_init(const float* __restrict__ unary) {
    int i = blockIdx.x * blockDim.x + threadIdx.x;
    if (i >= NPIX) return;
    float s = 0.f;
    const float* p = g_rowpart + i * MTILES;
#pragma unroll
    for (int b = 0; b < MTILES; ++b) s += p[b];
    float ri = 1.0f / (sqrtf(s) + 1e-8f);
    g_rowinv[i] = ri;

    float L[NCH];
    float m = -1e30f;
#pragma unroll
    for (int c = 0; c < NCH; ++c) {
        float u = unary[c * NPIX + i];
        u = fminf(fmaxf(u, 1e-5f), 1.0f);
        float lu = logf(u);
        g_U[c * NPIX + i] = lu;
        L[c] = lu;
        m = fmaxf(m, lu);
    }
    float se = 0.f;
#pragma unroll
    for (int c = 0; c < NCH; ++c) { L[c] = __expf(L[c] - m); se += L[c]; }
    float inv = 1.0f / se;
#pragma unroll
    for (int c = 0; c < NCH; ++c) {
        float q = L[c] * inv;
        g_q[c * NPIX + i] = q;
        g_qh[c * NPIX + i] = __float2half_rn(q * ri);
    }
#pragma unroll
    for (int c = NCH; c < 32; ++c) g_qh[c * NPIX + i] = __float2half_rn(0.f);
}

// ---------------- strip-parallel separable conv, zero-padded + unrolled ----------------
// grid = NCH * STRIPS (126 CTAs). Fixed 71-tap loops, 4-way ILP.
__global__ void __launch_bounds__(384) k_conv() {
    __shared__ float sImg[HALO * HW];     // fixed window, zero-padded
    __shared__ float sTmp[SROWS * TROW];  // padded rows
    __shared__ float sW[KW];
    const int c = blockIdx.x / STRIPS;
    const int strip = blockIdx.x % STRIPS;
    const int y0 = strip * SROWS;
    const int rowLo = y0 - RAD;           // may be negative
    const int tid = threadIdx.x;

    if (tid < KW) sW[tid] = g_g1d[tid];
    const float* src = g_q + c * NPIX;
    for (int p = tid; p < HALO * HW; p += 384) {
        int r = p / HW, x = p - r * HW;
        int gr = rowLo + r;
        sImg[p] = (gr >= 0 && gr < HW) ? src[gr * HW + x] : 0.f;
    }
    for (int p = tid; p < SROWS * TROW; p += 384) sTmp[p] = 0.f;
    __syncthreads();

    // Y pass: output (yy, x) needs sImg rows yy..yy+70 at column x
    for (int p = tid; p < SROWS * HW; p += 384) {
        int yy = p / HW, x = p - yy * HW;
        const float* col = sImg + yy * HW + x;
        float s0 = 0.f, s1 = 0.f, s2 = 0.f, s3 = 0.f;
#pragma unroll
        for (int t = 0; t < 68; t += 4) {
            s0 = fmaf(sW[t],     col[t * HW],       s0);
            s1 = fmaf(sW[t + 1], col[(t + 1) * HW], s1);
            s2 = fmaf(sW[t + 2], col[(t + 2) * HW], s2);
            s3 = fmaf(sW[t + 3], col[(t + 3) * HW], s3);
        }
        s0 = fmaf(sW[68], col[68 * HW], s0);
        s1 = fmaf(sW[69], col[69 * HW], s1);
        s2 = fmaf(sW[70], col[70 * HW], s2);
        sTmp[yy * TROW + RAD + x] = (s0 + s1) + (s2 + s3);
    }
    __syncthreads();

    // X pass: output (yy, x) needs sTmp[yy][x .. x+70]
    float* dst = g_qsf + c * NPIX + y0 * HW;
    for (int p = tid; p < SROWS * HW; p += 384) {
        int yy = p / HW, x = p - yy * HW;
        const float* row = sTmp + yy * TROW + x;
        float s0 = 0.f, s1 = 0.f, s2 = 0.f, s3 = 0.f;
#pragma unroll
        for (int t = 0; t < 68; t += 4) {
            s0 = fmaf(sW[t],     row[t],     s0);
            s1 = fmaf(sW[t + 1], row[t + 1], s1);
            s2 = fmaf(sW[t + 2], row[t + 2], s2);
            s3 = fmaf(sW[t + 3], row[t + 3], s3);
        }
        s0 = fmaf(sW[68], row[68], s0);
        s1 = fmaf(sW[69], row[69], s1);
        s2 = fmaf(sW[70], row[70], s2);
        dst[p] = (s0 + s1) + (s2 + s3);
    }
}

// ---------------- HMMA split-K GEMM, single-barrier pipeline ----------------
__global__ void __launch_bounds__(256, 1) k_gemm_mma() {
    extern __shared__ char dynRaw[];
    const uint32_t dynb = (s2u(dynRaw) + 1023u) & ~1023u;
    const int tid = threadIdx.x, w = tid >> 5, lid = tid & 31;
    const int m0 = blockIdx.x * 128;
    const int zbase = blockIdx.y * KHALF;

    const __half* Abase = g_Kh + (size_t)m0 * NPIX + zbase;
    const __half* Bbase = g_qh + zbase;

    auto load_chunk = [&](int ci) {
        const uint32_t stage = dynb + (uint32_t)(ci % NSTAGE) * STAGE_BYTES;
        const int koff = ci * CHUNK;
#pragma unroll
        for (int pl = 0; pl < 2; ++pl) {
            const uint32_t bufA = stage + (uint32_t)pl * PANEL_A;
            const uint32_t bufB = stage + 2 * PANEL_A + (uint32_t)pl * PANEL_B;
            const int kof = koff + pl * 64;
#pragma unroll
            for (int u = tid; u < 1280; u += 256) {
                uint32_t dst; const void* src;
                if (u < 1024) {
                    int r = u >> 3, t = u & 7;
                    src = Abase + (size_t)r * NPIX + kof + t * 8;
                    dst = bufA + SWZ((uint32_t)(r * 128 + t * 16));
                } else {
                    int v = u - 1024;
                    int cc = v >> 3, t = v & 7;
                    src = Bbase + (size_t)cc * NPIX + kof + t * 8;
                    dst = bufB + SWZ((uint32_t)(cc * 128 + t * 16));
                }
                CP16(dst, src);
            }
        }
        CP_COMMIT();
    };

    float acc[3][4];
#pragma unroll
    for (int g = 0; g < 3; ++g)
#pragma unroll
        for (int k = 0; k < 4; ++k) acc[g][k] = 0.f;

    for (int i = 0; i < NSTAGE - 1; ++i) load_chunk(i);

    const uint32_t aRowOff = (uint32_t)((w * 16 + (lid & 15)) * 128) + ((lid >> 4) << 4);
    const uint32_t bRowOff01 = (uint32_t)(((lid & 7) + ((lid >> 4) << 3)) * 128) + (((lid >> 3) & 1) << 4);
    const uint32_t bRowOff2 = (uint32_t)((16 + (lid & 7)) * 128) + (((lid >> 3) & 1) << 4);

    for (int i = 0; i < NCHUNK; ++i) {
        if (i + NSTAGE - 1 < NCHUNK) CP_WAIT(NSTAGE - 2); else CP_WAIT(0);
        __syncthreads();
        if (i + NSTAGE - 1 < NCHUNK) load_chunk(i + NSTAGE - 1);

        const uint32_t stage = dynb + (uint32_t)(i % NSTAGE) * STAGE_BYTES;
#pragma unroll
        for (int pl = 0; pl < 2; ++pl) {
            const uint32_t bufA = stage + (uint32_t)pl * PANEL_A;
            const uint32_t bufB = stage + 2 * PANEL_A + (uint32_t)pl * PANEL_B;
#pragma unroll
            for (int ks = 0; ks < 4; ++ks) {
                const uint32_t kb = (uint32_t)ks * 32;
                uint32_t a0, a1, a2, a3;
                LDSM4(a0, a1, a2, a3, bufA + SWZ(aRowOff + kb));
                uint32_t b00, b01, b10, b11, b20, b21;
                LDSM4(b00, b01, b10, b11, bufB + SWZ(bRowOff01 + kb));
                LDSM2(b20, b21, bufB + SWZ(bRowOff2 + kb));
                MMA16816(acc[0], a0, a1, a2, a3, b00, b01);
                MMA16816(acc[1], a0, a1, a2, a3, b10, b11);
                MMA16816(acc[2], a0, a1, a2, a3, b20, b21);
            }
        }
    }

    const int row0 = m0 + w * 16 + (lid >> 2);
    const int c0 = (lid & 3) * 2;
    float* pp = g_part + (size_t)blockIdx.y * (NCH * NPIX);
#pragma unroll
    for (int g = 0; g < 3; ++g) {
#pragma unroll
        for (int k = 0; k < 4; ++k) {
            int c = g * 8 + c0 + (k & 1);
            int row = row0 + ((k >> 1) << 3);
            if (c < NCH) pp[c * NPIX + row] = acc[g][k];
        }
    }
}

// ---------------- softmax update ----------------
__global__ void k_update(float* __restrict__ out, int final_it) {
    int i = blockIdx.x * blockDim.x + threadIdx.x;
    if (i >= NPIX) return;
    float ri = g_rowinv[i];
    float* dst = final_it ? out : g_q;

    float L[NCH];
    float m = -1e30f;
#pragma unroll
    for (int c = 0; c < NCH; ++c) {
        float s = g_part[c * NPIX + i] + g_part[(NCH + c) * NPIX + i];
        float l = g_U[c * NPIX + i] + 4.0f * (s * ri) + 2.0f * g_qsf[c * NPIX + i];
        L[c] = l;
        m = fmaxf(m, l);
    }
    float se = 0.f;
#pragma unroll
    for (int c = 0; c < NCH; ++c) { L[c] = __expf(L[c] - m); se += L[c]; }
    float inv = 1.0f / se;
#pragma unroll
    for (int c = 0; c < NCH; ++c) {
        float q = L[c] * inv;
        dst[c * NPIX + i] = q;
        g_qh[c * NPIX + i] = __float2half_rn(q * ri);
    }
}

// ---------------- launch ----------------
extern "C" void kernel_launch(void* const* d_in, const int* in_sizes, int n_in,
                              void* d_out, int out_size) {
    const float* unary = nullptr;
    const float* ref = nullptr;
    const float* kstd = nullptr;
    for (int i = 0; i < n_in; ++i) {
        if (in_sizes[i] == NCH * NPIX) unary = (const float*)d_in[i];
        else if (in_sizes[i] == 3 * NPIX) ref = (const float*)d_in[i];
        else if (in_sizes[i] == 5) kstd = (const float*)d_in[i];
    }

    cudaFuncSetAttribute(k_gemm_mma, cudaFuncAttributeMaxDynamicSharedMemorySize, GEMM_SMEM);

    k_feat<<<(NPIX + 255) / 256, 256>>>(ref, kstd);
    k_K<<<dim3(NPIX / 128, NPIX / 32), 256>>>();
    k_init<<<(NPIX + 255) / 256, 256>>>(unary);

    for (int it = 0; it < 5; ++it) {
        k_conv<<<NCH * STRIPS, 384>>>();
        k_gemm_mma<<<dim3(MTILES, KSPLIT), 256, GEMM_SMEM>>>();
        k_update<<<(NPIX + 255) / 256, 256>>>((float*)d_out, it == 4 ? 1 : 0);
    }
}